// round 9
// baseline (speedup 1.0000x reference)
#include <cuda_runtime.h>
#include <cstdint>

// ---------------------------------------------------------------------------
// R8: two-kernel fused involution for GB300 (sm_103a).
// vs R7 (keep skeleton): weights stored UNDUPLICATED (float4 = 4 distinct
// k/o per 16B); f32x2 dup pairs built in registers (ALU movs) instead of
// being re-read from smem every cc step. Phase-2: 2 LDS.128 -> 8 FFMA2.
// Kernel A: 128-thread blocks, all threads compute. Kernel B: SPLIT=8.
// ---------------------------------------------------------------------------

#define U64 unsigned long long

__device__ __forceinline__ U64 ffma2(U64 a, U64 b, U64 c) {
    U64 d;
    asm("fma.rn.f32x2 %0, %1, %2, %3;" : "=l"(d) : "l"(a), "l"(b), "l"(c));
    return d;
}
__device__ __forceinline__ U64 pack2(float lo, float hi) {
    U64 d;
    asm("mov.b64 %0, {%1, %2};" : "=l"(d) : "f"(lo), "f"(hi));
    return d;
}
__device__ __forceinline__ float2 unpack2(U64 v) {
    float2 r;
    asm("mov.b64 {%0, %1}, %2;" : "=f"(r.x), "=f"(r.y) : "l"(v));
    return r;
}
__device__ __forceinline__ void cp_async16(void* s, const void* g) {
    uint32_t sa = (uint32_t)__cvta_generic_to_shared(s);
    asm volatile("cp.async.cg.shared.global [%0], [%1], 16;" :: "r"(sa), "l"(g));
}
__device__ __forceinline__ void cp_async16z(void* s, const void* g, int srcbytes) {
    uint32_t sa = (uint32_t)__cvta_generic_to_shared(s);
    asm volatile("cp.async.cg.shared.global [%0], [%1], 16, %2;"
                 :: "r"(sa), "l"(g), "r"(srcbytes));
}
__device__ __forceinline__ void cp_commit()  { asm volatile("cp.async.commit_group;"); }
__device__ __forceinline__ void cp_wait1()   { asm volatile("cp.async.wait_group 1;"); }
__device__ __forceinline__ void cp_wait0()   { asm volatile("cp.async.wait_group 0;"); }

namespace cfg {
constexpr int C   = 256;
constexpr int HW  = 56;
constexpr int G   = 16;
constexpr int Cg  = 16;
constexpr int KS  = 7;
constexpr int PAD = 3;
constexpr int CR  = 64;
constexpr float EPSV = 1e-5f;

constexpr int TH = 4, TW = 8;
constexpr int TP = TH * TW;               // 32 pixels / tile
constexpr int HALO_H  = TH + 2 * PAD;     // 10 rows
constexpr int HALO_WP = 16;               // padded width, base col = w0-4
constexpr int HALO_CH = HALO_H * HALO_WP; // 160 floats per channel
constexpr int SPLIT = 8;                  // 2 groups per block

// Kernel A smem: W1u float4[64][17] (undup, padded) + xs[64][32]
constexpr int W1U_ROW  = 17;                       // float4 units per cc row
constexpr int A_OFF_XS = 64 * W1U_ROW * 4;         // 4352
constexpr int A_SMEM_FLOATS = A_OFF_XS + 2048;     // 6400 = 25 KiB

// Kernel B smem
constexpr int B_OFF_TS  = 0;                              // ts[64][32] 2048
constexpr int W2U_ROW   = 14;                             // float4 units (13 used)
constexpr int B_OFF_W2U = 2048;                           // 64*14*4 = 3584
constexpr int B_OFF_WG  = B_OFF_W2U + 64 * W2U_ROW * 4;   // 5632
constexpr int B_OFF_XH  = B_OFF_WG + 49 * TP;             // 7200
constexpr int B_SMEM_FLOATS = B_OFF_XH + Cg * HALO_CH;    // 9760 = 38.1 KiB
}
using namespace cfg;

__device__ float t_buf[4 * CR * HW * HW];   // 3.2 MB scratch

// ===========================================================================
// Kernel A: t = relu(BN(x @ W1^T + b1)), 128 threads, 4o x 4px per thread
// ===========================================================================
__global__ void __launch_bounds__(128) t_gemm_kernel(
    const float* __restrict__ x,
    const float* __restrict__ W1, const float* __restrict__ b1,
    const float* __restrict__ gamma, const float* __restrict__ beta,
    const float* __restrict__ mean, const float* __restrict__ var)
{
    extern __shared__ float smem[];
    float4* W1u = (float4*)smem;            // [cc][17]: unit oq = W1[4oq..4oq+3][cc]
    float* xs = smem + A_OFF_XS;            // [64ch][32px]

    const int tid = threadIdx.x;
    const int b   = blockIdx.z;
    const int h0  = blockIdx.y * TH;
    const int w0  = blockIdx.x * TW;
    const int oq  = tid >> 3;               // 0..15: outs 4oq..4oq+3
    const int pxq = tid & 7;                // px 4pxq..4pxq+3
    U64 q0a = 0, q0b = 0, q1a = 0, q1b = 0, q2a = 0, q2b = 0, q3a = 0, q3b = 0;

    for (int chunk = 0; chunk < 4; chunk++) {
        const int c0 = chunk * 64;
        {
            int u = tid;
            #pragma unroll
            for (int r = 0; r < 4; r++) {      // 512 float4 units
                const int cc = u >> 3, py = (u >> 1) & 3, hf = u & 1;
                const float4 v = *(const float4*)&x[((b * C + c0 + cc) * HW + h0 + py) * HW + w0 + hf * 4];
                *(float4*)&xs[cc * TP + py * TW + hf * 4] = v;
                u += 128;
            }
        }
        {
            int u = tid;
            #pragma unroll
            for (int r = 0; r < 8; r++) {      // 1024 units = [cc][16]
                const int cc = u >> 4, oo = (u & 15) * 4;
                float4 wv;
                wv.x = __ldg(&W1[(oo + 0) * C + c0 + cc]);
                wv.y = __ldg(&W1[(oo + 1) * C + c0 + cc]);
                wv.z = __ldg(&W1[(oo + 2) * C + c0 + cc]);
                wv.w = __ldg(&W1[(oo + 3) * C + c0 + cc]);
                W1u[cc * W1U_ROW + (u & 15)] = wv;
                u += 128;
            }
        }
        __syncthreads();

        #pragma unroll 8
        for (int cc = 0; cc < 64; cc++) {
            const ulonglong2 tv = *(const ulonglong2*)&xs[cc * TP + pxq * 4];
            const float4 wq = W1u[cc * W1U_ROW + oq];
            const U64 d0 = pack2(wq.x, wq.x);
            const U64 d1 = pack2(wq.y, wq.y);
            const U64 d2 = pack2(wq.z, wq.z);
            const U64 d3 = pack2(wq.w, wq.w);
            q0a = ffma2(d0, tv.x, q0a); q0b = ffma2(d0, tv.y, q0b);
            q1a = ffma2(d1, tv.x, q1a); q1b = ffma2(d1, tv.y, q1b);
            q2a = ffma2(d2, tv.x, q2a); q2b = ffma2(d2, tv.y, q2b);
            q3a = ffma2(d3, tv.x, q3a); q3b = ffma2(d3, tv.y, q3b);
        }
        __syncthreads();
    }

    {
        const int py = pxq >> 1, pw = (pxq & 1) * 4;
        U64 qa[4] = {q0a, q1a, q2a, q3a};
        U64 qb[4] = {q0b, q1b, q2b, q3b};
        #pragma unroll
        for (int u = 0; u < 4; u++) {
            const int o = 4 * oq + u;
            const float a  = __ldg(&gamma[o]) * rsqrtf(__ldg(&var[o]) + EPSV);
            const float bb = __ldg(&b1[o]) * a + __ldg(&beta[o]) - __ldg(&mean[o]) * a;
            const float2 p0 = unpack2(qa[u]);
            const float2 p1 = unpack2(qb[u]);
            float4 r;
            r.x = fmaxf(p0.x * a + bb, 0.f);
            r.y = fmaxf(p0.y * a + bb, 0.f);
            r.z = fmaxf(p1.x * a + bb, 0.f);
            r.w = fmaxf(p1.y * a + bb, 0.f);
            *(float4*)&t_buf[((b * CR + o) * HW + h0 + py) * HW + w0 + pw] = r;
        }
    }
}

// ===========================================================================
// Kernel B: kernel-GEMM (undup weights) + involution, 2 groups per block
// ===========================================================================
__global__ void __launch_bounds__(256) involution_kernel(
    const float* __restrict__ x,
    const float* __restrict__ W2, const float* __restrict__ b2,
    float* __restrict__ out)
{
    extern __shared__ float smem[];
    float* ts = smem + B_OFF_TS;                    // [64cc][32px]
    float4* W2u = (float4*)(smem + B_OFF_W2U);      // [cc][14]: unit kq = W2[4kq..4kq+3][cc]
    float* wg = smem + B_OFF_WG;                    // [49k][32px]
    float* xh = smem + B_OFF_XH;                    // [16c][10][16]

    const int tid = threadIdx.x;
    const int z   = blockIdx.z;
    const int b   = z >> 3;
    const int gs  = z & 7;
    const int h0  = blockIdx.y * TH;
    const int w0  = blockIdx.x * TW;

    // ts tile via cp.async16 (512 segments, 2 per thread)
    {
        int idx = tid;
        #pragma unroll
        for (int r = 0; r < 2; r++) {
            const int cc = idx >> 3, py = (idx >> 1) & 3, hf = idx & 1;
            cp_async16(&ts[cc * TP + py * TW + hf * 4],
                       &t_buf[((b * CR + cc) * HW + h0 + py) * HW + w0 + hf * 4]);
            idx += 256;
        }
        cp_commit();
    }

    // phase-2 ids: kq owns k = 4kq..4kq+3 (active kq<13), pxq2 owns 4 px
    const int kq   = tid >> 3;
    const int pxq2 = tid & 7;
    // phase-3 ids (threads 0..127): channels 2cs,2cs+1; pixel pair 2pxp,2pxp+1
    const int cs   = tid >> 4;
    const int pxp  = tid & 15;
    const int py3  = pxp >> 2;
    const int col3 = (pxp & 3) * 2;

    for (int gi = 0; gi < G / SPLIT; gi++) {
        const int g = gs * (G / SPLIT) + gi;

        // ---- halo: [16c][10 rows][4 seg of 16B], buffer col0 = w0-4, zfill
        {
            const float* xgb = &x[(size_t)(b * C + g * Cg) * HW * HW];
            int idx = tid;
            #pragma unroll
            for (int r4 = 0; r4 < 3; r4++) {       // 640 segments
                if (idx < Cg * HALO_H * 4) {
                    const int c   = idx / 40;      // 10 rows * 4 segs
                    const int rem = idx - c * 40;
                    const int rr  = rem >> 2;
                    const int s   = rem & 3;
                    const int gh  = h0 + rr - PAD;
                    const int gw0 = w0 - 4 + 4 * s;
                    int szb = 0;
                    if ((unsigned)gh < (unsigned)HW && gw0 >= 0) {
                        const int rem2 = HW - gw0;
                        szb = (rem2 >= 4 ? 4 : (rem2 > 0 ? rem2 : 0)) * 4;
                    }
                    const int ghc = gh < 0 ? 0 : (gh > HW - 1 ? HW - 1 : gh);
                    const int gwc = gw0 < 0 ? 0 : (gw0 > HW - 4 ? HW - 4 : gw0);
                    cp_async16z(&xh[c * HALO_CH + rr * HALO_WP + 4 * s],
                                &xgb[(c * HW + ghc) * HW + gwc], szb);
                }
                idx += 256;
            }
            cp_commit();
        }

        // ---- W2 group -> W2u[cc][kq] = (w_{4kq},..,w_{4kq+3}) undup
        {
            int idx = tid;
            #pragma unroll
            for (int r = 0; r < 4; r++) {          // 64*13 = 832 units
                if (idx < 832) {
                    const int cc = idx / 13;
                    const int kq4 = idx - cc * 13;
                    const int kbase = 4 * kq4;
                    float4 wv;
                    wv.x = __ldg(&W2[(g * 49 + kbase + 0) * CR + cc]);
                    wv.y = __ldg(&W2[(g * 49 + kbase + 1) * CR + cc]);
                    wv.z = __ldg(&W2[(g * 49 + kbase + 2) * CR + cc]);
                    wv.w = (kbase + 3 < 49) ? __ldg(&W2[(g * 49 + kbase + 3) * CR + cc]) : 0.f;
                    W2u[cc * W2U_ROW + kq4] = wv;
                }
                idx += 256;
            }
        }
        cp_wait1();            // ts landed (gi=0); halo may still be in flight
        __syncthreads();

        // ---- phase 2: wg[k][p] = sum_cc W2g[k][cc]*t[cc][p] + b2[k]
        if (kq < 13) {
            const int kbase = 4 * kq;
            float zb[4];
            #pragma unroll
            for (int kk = 0; kk < 4; kk++) {
                const int k = kbase + kk;
                zb[kk] = (k < 49) ? __ldg(&b2[g * 49 + k]) : 0.f;
            }
            U64 q0a = pack2(zb[0], zb[0]), q0b = q0a;
            U64 q1a = pack2(zb[1], zb[1]), q1b = q1a;
            U64 q2a = pack2(zb[2], zb[2]), q2b = q2a;
            U64 q3a = pack2(zb[3], zb[3]), q3b = q3a;
            #pragma unroll 8
            for (int cc = 0; cc < 64; cc++) {
                const ulonglong2 tv = *(const ulonglong2*)&ts[cc * TP + pxq2 * 4];
                const float4 wq = W2u[cc * W2U_ROW + kq];
                const U64 d0 = pack2(wq.x, wq.x);
                const U64 d1 = pack2(wq.y, wq.y);
                const U64 d2 = pack2(wq.z, wq.z);
                const U64 d3 = pack2(wq.w, wq.w);
                q0a = ffma2(d0, tv.x, q0a); q0b = ffma2(d0, tv.y, q0b);
                q1a = ffma2(d1, tv.x, q1a); q1b = ffma2(d1, tv.y, q1b);
                q2a = ffma2(d2, tv.x, q2a); q2b = ffma2(d2, tv.y, q2b);
                q3a = ffma2(d3, tv.x, q3a); q3b = ffma2(d3, tv.y, q3b);
            }
            U64 qa[4] = {q0a, q1a, q2a, q3a};
            U64 qb[4] = {q0b, q1b, q2b, q3b};
            #pragma unroll
            for (int kk = 0; kk < 4; kk++) {
                const int k = kbase + kk;
                if (k < 49) {
                    *(U64*)&wg[k * TP + pxq2 * 4]     = qa[kk];
                    *(U64*)&wg[k * TP + pxq2 * 4 + 2] = qb[kk];
                }
            }
        }
        cp_wait0();            // halo landed (overlapped with phase 2)
        __syncthreads();

        // ---- phase 3: thread owns (channels 2cs,2cs+1; pixels 2pxp,2pxp+1)
        if (tid < 128) {
            const int c0 = 2 * cs;
            const float* xa = &xh[c0 * HALO_CH + py3 * HALO_WP + col3];
            const float* xb = xa + HALO_CH;
            float o00 = 0.f, o01 = 0.f, o10 = 0.f, o11 = 0.f;
            #pragma unroll
            for (int i = 0; i < KS; i++) {
                const float* r0 = xa + i * HALO_WP;
                const float* r1 = xb + i * HALO_WP;
                float x0[10], x1[10];
                #pragma unroll
                for (int q = 0; q < 5; q++) {
                    const float2 v0 = *(const float2*)(r0 + 2 * q);
                    const float2 v1 = *(const float2*)(r1 + 2 * q);
                    x0[2 * q] = v0.x; x0[2 * q + 1] = v0.y;
                    x1[2 * q] = v1.x; x1[2 * q + 1] = v1.y;
                }
                #pragma unroll
                for (int j = 0; j < KS; j++) {
                    const float2 wv = *(const float2*)&wg[(i * KS + j) * TP + 2 * pxp];
                    o00 = fmaf(x0[j + 1], wv.x, o00);
                    o01 = fmaf(x0[j + 2], wv.y, o01);
                    o10 = fmaf(x1[j + 1], wv.x, o10);
                    o11 = fmaf(x1[j + 2], wv.y, o11);
                }
            }
            const int base = ((b * C + g * Cg + c0) * HW + h0 + py3) * HW + w0 + col3;
            *(float2*)&out[base]           = make_float2(o00, o01);
            *(float2*)&out[base + HW * HW] = make_float2(o10, o11);
        }
        __syncthreads();
    }
}

extern "C" void kernel_launch(void* const* d_in, const int* in_sizes, int n_in,
                              void* d_out, int out_size) {
    const float* x     = (const float*)d_in[0];
    const float* W1    = (const float*)d_in[1];
    const float* b1    = (const float*)d_in[2];
    const float* gamma = (const float*)d_in[3];
    const float* beta  = (const float*)d_in[4];
    const float* mean  = (const float*)d_in[5];
    const float* var   = (const float*)d_in[6];
    const float* W2    = (const float*)d_in[7];
    const float* b2    = (const float*)d_in[8];
    float* out = (float*)d_out;

    const size_t smemA = (size_t)A_SMEM_FLOATS * sizeof(float);
    const size_t smemB = (size_t)B_SMEM_FLOATS * sizeof(float);
    cudaFuncSetAttribute(t_gemm_kernel,
                         cudaFuncAttributeMaxDynamicSharedMemorySize, (int)smemA);
    cudaFuncSetAttribute(involution_kernel,
                         cudaFuncAttributeMaxDynamicSharedMemorySize, (int)smemB);

    dim3 gridA(HW / TW, HW / TH, 4);            // 392 blocks, 128 threads
    t_gemm_kernel<<<gridA, 128, smemA>>>(x, W1, b1, gamma, beta, mean, var);

    dim3 gridB(HW / TW, HW / TH, 4 * SPLIT);    // 3136 blocks
    involution_kernel<<<gridB, 256, smemB>>>(x, W2, b2, out);
}

// round 11
// speedup vs baseline: 1.0707x; 1.0707x over previous
#include <cuda_runtime.h>
#include <cstdint>

// ---------------------------------------------------------------------------
// R9: R7 (best, 119.3us) + exactly ONE change:
//   Kernel B stores W2 UNDUPLICATED (float4 = 4 distinct k per 16B) and
//   builds the f32x2 dup pairs in registers. Phase-2 inner loop:
//   2 LDS.128 -> 8 FFMA2 (was 3 LDS.128). Everything else identical to R7.
// ---------------------------------------------------------------------------

#define U64 unsigned long long

__device__ __forceinline__ U64 ffma2(U64 a, U64 b, U64 c) {
    U64 d;
    asm("fma.rn.f32x2 %0, %1, %2, %3;" : "=l"(d) : "l"(a), "l"(b), "l"(c));
    return d;
}
__device__ __forceinline__ U64 pack2(float lo, float hi) {
    U64 d;
    asm("mov.b64 %0, {%1, %2};" : "=l"(d) : "f"(lo), "f"(hi));
    return d;
}
__device__ __forceinline__ float2 unpack2(U64 v) {
    float2 r;
    asm("mov.b64 {%0, %1}, %2;" : "=f"(r.x), "=f"(r.y) : "l"(v));
    return r;
}
__device__ __forceinline__ void cp_async16(void* s, const void* g) {
    uint32_t sa = (uint32_t)__cvta_generic_to_shared(s);
    asm volatile("cp.async.cg.shared.global [%0], [%1], 16;" :: "r"(sa), "l"(g));
}
__device__ __forceinline__ void cp_async16z(void* s, const void* g, int srcbytes) {
    uint32_t sa = (uint32_t)__cvta_generic_to_shared(s);
    asm volatile("cp.async.cg.shared.global [%0], [%1], 16, %2;"
                 :: "r"(sa), "l"(g), "r"(srcbytes));
}
__device__ __forceinline__ void cp_commit()  { asm volatile("cp.async.commit_group;"); }
__device__ __forceinline__ void cp_wait1()   { asm volatile("cp.async.wait_group 1;"); }
__device__ __forceinline__ void cp_wait0()   { asm volatile("cp.async.wait_group 0;"); }

namespace cfg {
constexpr int C   = 256;
constexpr int HW  = 56;
constexpr int G   = 16;
constexpr int Cg  = 16;
constexpr int KS  = 7;
constexpr int PAD = 3;
constexpr int CR  = 64;
constexpr float EPSV = 1e-5f;

constexpr int TH = 4, TW = 8;
constexpr int TP = TH * TW;               // 32 pixels / tile
constexpr int HALO_H  = TH + 2 * PAD;     // 10 rows
constexpr int HALO_WP = 16;               // padded width, base col = w0-4
constexpr int HALO_CH = HALO_H * HALO_WP; // 160 floats per channel
constexpr int SPLIT = 4;                  // 4 groups per block (as R7)

// Kernel A smem: W1d float4[64][33] + xs[64][32]  (R7 verbatim)
constexpr int W1D_ROW  = 33;
constexpr int A_OFF_XS = 64 * W1D_ROW * 4;         // 8448
constexpr int A_SMEM_FLOATS = A_OFF_XS + 2048;     // 10496 = 41 KiB

// Kernel B smem (undup W2)
constexpr int B_OFF_TS  = 0;                              // ts[64][32] 2048
constexpr int W2U_ROW   = 14;                             // float4 units (13 used)
constexpr int B_OFF_W2U = 2048;                           // 64*14*4 = 3584
constexpr int B_OFF_WG  = B_OFF_W2U + 64 * W2U_ROW * 4;   // 5632
constexpr int B_OFF_XH  = B_OFF_WG + 49 * TP;             // 7200
constexpr int B_SMEM_FLOATS = B_OFF_XH + Cg * HALO_CH;    // 9760 = 38.1 KiB
}
using namespace cfg;

__device__ float t_buf[4 * CR * HW * HW];   // 3.2 MB scratch

// ===========================================================================
// Kernel A: t = relu(BN(x @ W1^T + b1)), R7 version verbatim
// ===========================================================================
__global__ void __launch_bounds__(256) t_gemm_kernel(
    const float* __restrict__ x,
    const float* __restrict__ W1, const float* __restrict__ b1,
    const float* __restrict__ gamma, const float* __restrict__ beta,
    const float* __restrict__ mean, const float* __restrict__ var)
{
    extern __shared__ float smem[];
    ulonglong2* W1d = (ulonglong2*)smem;    // [cc][33]: pair p = (W1[2p] dup | W1[2p+1] dup)
    float* xs = smem + A_OFF_XS;            // [64ch][32px]

    const int tid = threadIdx.x;
    const int b   = blockIdx.z;
    const int h0  = blockIdx.y * TH;
    const int w0  = blockIdx.x * TW;
    const int oq  = tid >> 3;               // active oq<16: outs 4oq..4oq+3
    const int pxq = tid & 7;                // px 4pxq..4pxq+3
    U64 q0a = 0, q0b = 0, q1a = 0, q1b = 0, q2a = 0, q2b = 0, q3a = 0, q3b = 0;

    for (int chunk = 0; chunk < 4; chunk++) {
        const int c0 = chunk * 64;
        {
            int idx = tid;
            #pragma unroll
            for (int r = 0; r < 2; r++) {
                const int cc = idx >> 3, py = (idx >> 1) & 3, hf = idx & 1;
                const float4 v = *(const float4*)&x[((b * C + c0 + cc) * HW + h0 + py) * HW + w0 + hf * 4];
                *(float4*)&xs[cc * TP + py * TW + hf * 4] = v;
                idx += 256;
            }
        }
        #pragma unroll
        for (int r = 0; r < 8; r++) {
            const int idx = tid + 256 * r;
            const int cc = idx & 63, o2 = idx >> 6;     // pair o2: 0..31
            const float v0 = __ldg(&W1[(2 * o2) * C + c0 + cc]);
            const float v1 = __ldg(&W1[(2 * o2 + 1) * C + c0 + cc]);
            *(float4*)&W1d[cc * W1D_ROW + o2] = make_float4(v0, v0, v1, v1);
        }
        __syncthreads();

        if (oq < 16) {
            #pragma unroll 8
            for (int cc = 0; cc < 64; cc++) {
                const ulonglong2 tv  = *(const ulonglong2*)&xs[cc * TP + pxq * 4];
                const ulonglong2 wva = W1d[cc * W1D_ROW + 2 * oq];
                const ulonglong2 wvb = W1d[cc * W1D_ROW + 2 * oq + 1];
                q0a = ffma2(wva.x, tv.x, q0a); q0b = ffma2(wva.x, tv.y, q0b);
                q1a = ffma2(wva.y, tv.x, q1a); q1b = ffma2(wva.y, tv.y, q1b);
                q2a = ffma2(wvb.x, tv.x, q2a); q2b = ffma2(wvb.x, tv.y, q2b);
                q3a = ffma2(wvb.y, tv.x, q3a); q3b = ffma2(wvb.y, tv.y, q3b);
            }
        }
        __syncthreads();
    }

    if (oq < 16) {
        const int py = pxq >> 1, pw = (pxq & 1) * 4;
        U64 qa[4] = {q0a, q1a, q2a, q3a};
        U64 qb[4] = {q0b, q1b, q2b, q3b};
        #pragma unroll
        for (int u = 0; u < 4; u++) {
            const int o = 4 * oq + u;
            const float a  = __ldg(&gamma[o]) * rsqrtf(__ldg(&var[o]) + EPSV);
            const float bb = __ldg(&b1[o]) * a + __ldg(&beta[o]) - __ldg(&mean[o]) * a;
            const float2 p0 = unpack2(qa[u]);
            const float2 p1 = unpack2(qb[u]);
            float4 r;
            r.x = fmaxf(p0.x * a + bb, 0.f);
            r.y = fmaxf(p0.y * a + bb, 0.f);
            r.z = fmaxf(p1.x * a + bb, 0.f);
            r.w = fmaxf(p1.y * a + bb, 0.f);
            *(float4*)&t_buf[((b * CR + o) * HW + h0 + py) * HW + w0 + pw] = r;
        }
    }
}

// ===========================================================================
// Kernel B: kernel-GEMM (undup W2) + involution, 4 groups per block
// ===========================================================================
__global__ void __launch_bounds__(256) involution_kernel(
    const float* __restrict__ x,
    const float* __restrict__ W2, const float* __restrict__ b2,
    float* __restrict__ out)
{
    extern __shared__ float smem[];
    float* ts = smem + B_OFF_TS;                    // [64cc][32px]
    float4* W2u = (float4*)(smem + B_OFF_W2U);      // [cc][14]: unit kq = W2[4kq..4kq+3][cc]
    float* wg = smem + B_OFF_WG;                    // [49k][32px]
    float* xh = smem + B_OFF_XH;                    // [16c][10][16]

    const int tid = threadIdx.x;
    const int z   = blockIdx.z;
    const int b   = z >> 2;
    const int gs  = z & 3;
    const int h0  = blockIdx.y * TH;
    const int w0  = blockIdx.x * TW;

    // ts tile via cp.async16 (512 segments, 2 per thread)
    {
        int idx = tid;
        #pragma unroll
        for (int r = 0; r < 2; r++) {
            const int cc = idx >> 3, py = (idx >> 1) & 3, hf = idx & 1;
            cp_async16(&ts[cc * TP + py * TW + hf * 4],
                       &t_buf[((b * CR + cc) * HW + h0 + py) * HW + w0 + hf * 4]);
            idx += 256;
        }
        cp_commit();
    }

    // phase-2 ids: kq owns k = 4kq..4kq+3 (active kq<13), pxq2 owns 4 px
    const int kq   = tid >> 3;
    const int pxq2 = tid & 7;
    // phase-3 ids (threads 0..127): channels 2cs,2cs+1; pixel pair 2pxp,2pxp+1
    const int cs   = tid >> 4;
    const int pxp  = tid & 15;
    const int py3  = pxp >> 2;
    const int col3 = (pxp & 3) * 2;

    for (int gi = 0; gi < G / SPLIT; gi++) {
        const int g = gs * (G / SPLIT) + gi;

        // ---- halo: [16c][10 rows][4 seg of 16B], buffer col0 = w0-4, zfill
        {
            const float* xgb = &x[(size_t)(b * C + g * Cg) * HW * HW];
            int idx = tid;
            #pragma unroll
            for (int r4 = 0; r4 < 3; r4++) {       // 640 segments
                if (idx < Cg * HALO_H * 4) {
                    const int c   = idx / 40;      // 10 rows * 4 segs
                    const int rem = idx - c * 40;
                    const int rr  = rem >> 2;
                    const int s   = rem & 3;
                    const int gh  = h0 + rr - PAD;
                    const int gw0 = w0 - 4 + 4 * s;
                    int szb = 0;
                    if ((unsigned)gh < (unsigned)HW && gw0 >= 0) {
                        const int rem2 = HW - gw0;
                        szb = (rem2 >= 4 ? 4 : (rem2 > 0 ? rem2 : 0)) * 4;
                    }
                    const int ghc = gh < 0 ? 0 : (gh > HW - 1 ? HW - 1 : gh);
                    const int gwc = gw0 < 0 ? 0 : (gw0 > HW - 4 ? HW - 4 : gw0);
                    cp_async16z(&xh[c * HALO_CH + rr * HALO_WP + 4 * s],
                                &xgb[(c * HW + ghc) * HW + gwc], szb);
                }
                idx += 256;
            }
            cp_commit();
        }

        // ---- W2 group -> W2u[cc][kq] = (w_{4kq},..,w_{4kq+3}) undup
        {
            int idx = tid;
            #pragma unroll
            for (int r = 0; r < 4; r++) {          // 64*13 = 832 units
                if (idx < 832) {
                    const int cc = idx / 13;
                    const int kq4 = idx - cc * 13;
                    const int kbase = 4 * kq4;
                    float4 wv;
                    wv.x = __ldg(&W2[(g * 49 + kbase + 0) * CR + cc]);
                    wv.y = __ldg(&W2[(g * 49 + kbase + 1) * CR + cc]);
                    wv.z = __ldg(&W2[(g * 49 + kbase + 2) * CR + cc]);
                    wv.w = (kbase + 3 < 49) ? __ldg(&W2[(g * 49 + kbase + 3) * CR + cc]) : 0.f;
                    W2u[cc * W2U_ROW + kq4] = wv;
                }
                idx += 256;
            }
        }
        cp_wait1();            // ts landed (gi=0); halo may still be in flight
        __syncthreads();

        // ---- phase 2: wg[k][p] = sum_cc W2g[k][cc]*t[cc][p] + b2[k]
        if (kq < 13) {
            const int kbase = 4 * kq;
            float zb[4];
            #pragma unroll
            for (int kk = 0; kk < 4; kk++) {
                const int k = kbase + kk;
                zb[kk] = (k < 49) ? __ldg(&b2[g * 49 + k]) : 0.f;
            }
            U64 q0a = pack2(zb[0], zb[0]), q0b = q0a;
            U64 q1a = pack2(zb[1], zb[1]), q1b = q1a;
            U64 q2a = pack2(zb[2], zb[2]), q2b = q2a;
            U64 q3a = pack2(zb[3], zb[3]), q3b = q3a;
            #pragma unroll 8
            for (int cc = 0; cc < 64; cc++) {
                const ulonglong2 tv = *(const ulonglong2*)&ts[cc * TP + pxq2 * 4];
                const float4 wq = W2u[cc * W2U_ROW + kq];
                const U64 d0 = pack2(wq.x, wq.x);
                const U64 d1 = pack2(wq.y, wq.y);
                const U64 d2 = pack2(wq.z, wq.z);
                const U64 d3 = pack2(wq.w, wq.w);
                q0a = ffma2(d0, tv.x, q0a); q0b = ffma2(d0, tv.y, q0b);
                q1a = ffma2(d1, tv.x, q1a); q1b = ffma2(d1, tv.y, q1b);
                q2a = ffma2(d2, tv.x, q2a); q2b = ffma2(d2, tv.y, q2b);
                q3a = ffma2(d3, tv.x, q3a); q3b = ffma2(d3, tv.y, q3b);
            }
            U64 qa[4] = {q0a, q1a, q2a, q3a};
            U64 qb[4] = {q0b, q1b, q2b, q3b};
            #pragma unroll
            for (int kk = 0; kk < 4; kk++) {
                const int k = kbase + kk;
                if (k < 49) {
                    *(U64*)&wg[k * TP + pxq2 * 4]     = qa[kk];
                    *(U64*)&wg[k * TP + pxq2 * 4 + 2] = qb[kk];
                }
            }
        }
        cp_wait0();            // halo landed (overlapped with phase 2)
        __syncthreads();

        // ---- phase 3: thread owns (channels 2cs,2cs+1; pixels 2pxp,2pxp+1)
        if (tid < 128) {
            const int c0 = 2 * cs;
            const float* xa = &xh[c0 * HALO_CH + py3 * HALO_WP + col3];
            const float* xb = xa + HALO_CH;
            float o00 = 0.f, o01 = 0.f, o10 = 0.f, o11 = 0.f;
            #pragma unroll
            for (int i = 0; i < KS; i++) {
                const float* r0 = xa + i * HALO_WP;
                const float* r1 = xb + i * HALO_WP;
                float x0[10], x1[10];
                #pragma unroll
                for (int q = 0; q < 5; q++) {
                    const float2 v0 = *(const float2*)(r0 + 2 * q);
                    const float2 v1 = *(const float2*)(r1 + 2 * q);
                    x0[2 * q] = v0.x; x0[2 * q + 1] = v0.y;
                    x1[2 * q] = v1.x; x1[2 * q + 1] = v1.y;
                }
                #pragma unroll
                for (int j = 0; j < KS; j++) {
                    const float2 wv = *(const float2*)&wg[(i * KS + j) * TP + 2 * pxp];
                    o00 = fmaf(x0[j + 1], wv.x, o00);
                    o01 = fmaf(x0[j + 2], wv.y, o01);
                    o10 = fmaf(x1[j + 1], wv.x, o10);
                    o11 = fmaf(x1[j + 2], wv.y, o11);
                }
            }
            const int base = ((b * C + g * Cg + c0) * HW + h0 + py3) * HW + w0 + col3;
            *(float2*)&out[base]           = make_float2(o00, o01);
            *(float2*)&out[base + HW * HW] = make_float2(o10, o11);
        }
        __syncthreads();
    }
}

extern "C" void kernel_launch(void* const* d_in, const int* in_sizes, int n_in,
                              void* d_out, int out_size) {
    const float* x     = (const float*)d_in[0];
    const float* W1    = (const float*)d_in[1];
    const float* b1    = (const float*)d_in[2];
    const float* gamma = (const float*)d_in[3];
    const float* beta  = (const float*)d_in[4];
    const float* mean  = (const float*)d_in[5];
    const float* var   = (const float*)d_in[6];
    const float* W2    = (const float*)d_in[7];
    const float* b2    = (const float*)d_in[8];
    float* out = (float*)d_out;

    const size_t smemA = (size_t)A_SMEM_FLOATS * sizeof(float);
    const size_t smemB = (size_t)B_SMEM_FLOATS * sizeof(float);
    cudaFuncSetAttribute(t_gemm_kernel,
                         cudaFuncAttributeMaxDynamicSharedMemorySize, (int)smemA);
    cudaFuncSetAttribute(involution_kernel,
                         cudaFuncAttributeMaxDynamicSharedMemorySize, (int)smemB);

    dim3 gridA(HW / TW, HW / TH, 4);            // 392 blocks
    t_gemm_kernel<<<gridA, 256, smemA>>>(x, W1, b1, gamma, beta, mean, var);

    dim3 gridB(HW / TW, HW / TH, 4 * SPLIT);    // 1568 blocks
    involution_kernel<<<gridB, 256, smemB>>>(x, W2, b2, out);
}

// round 12
// speedup vs baseline: 1.0971x; 1.0246x over previous
#include <cuda_runtime.h>
#include <cstdint>

// ---------------------------------------------------------------------------
// R11: R7 phase code verbatim + WARP SPECIALIZATION in kernel B:
//   warps 0-3 (producers): phase-2 kernel-GEMM for group i
//   warps 4-7 (consumers): phase-3 involution for group i-1 + halo prefetch
//   wg double-buffered; xh single-buffered (1-iter lookahead);
//   named barriers per half; one __syncthreads per pipeline step.
// Attacks measured issue=27-33% / active-warps deficit (latency bound).
// ---------------------------------------------------------------------------

#define U64 unsigned long long

__device__ __forceinline__ U64 ffma2(U64 a, U64 b, U64 c) {
    U64 d;
    asm("fma.rn.f32x2 %0, %1, %2, %3;" : "=l"(d) : "l"(a), "l"(b), "l"(c));
    return d;
}
__device__ __forceinline__ U64 pack2(float lo, float hi) {
    U64 d;
    asm("mov.b64 %0, {%1, %2};" : "=l"(d) : "f"(lo), "f"(hi));
    return d;
}
__device__ __forceinline__ float2 unpack2(U64 v) {
    float2 r;
    asm("mov.b64 {%0, %1}, %2;" : "=f"(r.x), "=f"(r.y) : "l"(v));
    return r;
}
__device__ __forceinline__ void cp_async16(void* s, const void* g) {
    uint32_t sa = (uint32_t)__cvta_generic_to_shared(s);
    asm volatile("cp.async.cg.shared.global [%0], [%1], 16;" :: "r"(sa), "l"(g));
}
__device__ __forceinline__ void cp_async16z(void* s, const void* g, int srcbytes) {
    uint32_t sa = (uint32_t)__cvta_generic_to_shared(s);
    asm volatile("cp.async.cg.shared.global [%0], [%1], 16, %2;"
                 :: "r"(sa), "l"(g), "r"(srcbytes));
}
__device__ __forceinline__ void cp_commit()  { asm volatile("cp.async.commit_group;"); }
__device__ __forceinline__ void cp_wait0()   { asm volatile("cp.async.wait_group 0;"); }
__device__ __forceinline__ void barx(int id) {
    asm volatile("bar.sync %0, 128;" :: "r"(id) : "memory");
}

namespace cfg {
constexpr int C   = 256;
constexpr int HW  = 56;
constexpr int G   = 16;
constexpr int Cg  = 16;
constexpr int KS  = 7;
constexpr int PAD = 3;
constexpr int CR  = 64;
constexpr float EPSV = 1e-5f;

constexpr int TH = 4, TW = 8;
constexpr int TP = TH * TW;               // 32 pixels / tile
constexpr int HALO_H  = TH + 2 * PAD;     // 10 rows
constexpr int HALO_WP = 16;               // padded width, base col = w0-4
constexpr int HALO_CH = HALO_H * HALO_WP; // 160 floats per channel
constexpr int SPLIT = 4;                  // 4 groups per block
constexpr int GPB   = G / SPLIT;          // 4

// Kernel A smem: W1d float4[64][33] + xs[64][32]  (R7 verbatim)
constexpr int W1D_ROW  = 33;
constexpr int A_OFF_XS = 64 * W1D_ROW * 4;         // 8448
constexpr int A_SMEM_FLOATS = A_OFF_XS + 2048;     // 10496 = 41 KiB

// Kernel B smem (dup W2d as R7; wg double-buffered; xh single)
constexpr int B_OFF_TS  = 0;                              // ts[64][32]   2048
constexpr int W2D_ROW   = 26;                             // float4 units (pair 25 = 0)
constexpr int B_OFF_W2D = 2048;                           // 64*26*4 = 6656
constexpr int B_OFF_WG  = B_OFF_W2D + 64 * W2D_ROW * 4;   // 8704
constexpr int WG_SZ     = 49 * TP;                        // 1568 (x2 buffers)
constexpr int B_OFF_XH  = B_OFF_WG + 2 * WG_SZ;           // 11840
constexpr int B_SMEM_FLOATS = B_OFF_XH + Cg * HALO_CH;    // 14400 = 56.25 KiB
}
using namespace cfg;

__device__ float t_buf[4 * CR * HW * HW];   // 3.2 MB scratch

// ===========================================================================
// Kernel A: t = relu(BN(x @ W1^T + b1)), R7 version verbatim
// ===========================================================================
__global__ void __launch_bounds__(256) t_gemm_kernel(
    const float* __restrict__ x,
    const float* __restrict__ W1, const float* __restrict__ b1,
    const float* __restrict__ gamma, const float* __restrict__ beta,
    const float* __restrict__ mean, const float* __restrict__ var)
{
    extern __shared__ float smem[];
    ulonglong2* W1d = (ulonglong2*)smem;    // [cc][33]: pair p = (W1[2p] dup | W1[2p+1] dup)
    float* xs = smem + A_OFF_XS;            // [64ch][32px]

    const int tid = threadIdx.x;
    const int b   = blockIdx.z;
    const int h0  = blockIdx.y * TH;
    const int w0  = blockIdx.x * TW;
    const int oq  = tid >> 3;               // active oq<16: outs 4oq..4oq+3
    const int pxq = tid & 7;                // px 4pxq..4pxq+3
    U64 q0a = 0, q0b = 0, q1a = 0, q1b = 0, q2a = 0, q2b = 0, q3a = 0, q3b = 0;

    for (int chunk = 0; chunk < 4; chunk++) {
        const int c0 = chunk * 64;
        {
            int idx = tid;
            #pragma unroll
            for (int r = 0; r < 2; r++) {
                const int cc = idx >> 3, py = (idx >> 1) & 3, hf = idx & 1;
                const float4 v = *(const float4*)&x[((b * C + c0 + cc) * HW + h0 + py) * HW + w0 + hf * 4];
                *(float4*)&xs[cc * TP + py * TW + hf * 4] = v;
                idx += 256;
            }
        }
        #pragma unroll
        for (int r = 0; r < 8; r++) {
            const int idx = tid + 256 * r;
            const int cc = idx & 63, o2 = idx >> 6;     // pair o2: 0..31
            const float v0 = __ldg(&W1[(2 * o2) * C + c0 + cc]);
            const float v1 = __ldg(&W1[(2 * o2 + 1) * C + c0 + cc]);
            *(float4*)&W1d[cc * W1D_ROW + o2] = make_float4(v0, v0, v1, v1);
        }
        __syncthreads();

        if (oq < 16) {
            #pragma unroll 8
            for (int cc = 0; cc < 64; cc++) {
                const ulonglong2 tv  = *(const ulonglong2*)&xs[cc * TP + pxq * 4];
                const ulonglong2 wva = W1d[cc * W1D_ROW + 2 * oq];
                const ulonglong2 wvb = W1d[cc * W1D_ROW + 2 * oq + 1];
                q0a = ffma2(wva.x, tv.x, q0a); q0b = ffma2(wva.x, tv.y, q0b);
                q1a = ffma2(wva.y, tv.x, q1a); q1b = ffma2(wva.y, tv.y, q1b);
                q2a = ffma2(wvb.x, tv.x, q2a); q2b = ffma2(wvb.x, tv.y, q2b);
                q3a = ffma2(wvb.y, tv.x, q3a); q3b = ffma2(wvb.y, tv.y, q3b);
            }
        }
        __syncthreads();
    }

    if (oq < 16) {
        const int py = pxq >> 1, pw = (pxq & 1) * 4;
        U64 qa[4] = {q0a, q1a, q2a, q3a};
        U64 qb[4] = {q0b, q1b, q2b, q3b};
        #pragma unroll
        for (int u = 0; u < 4; u++) {
            const int o = 4 * oq + u;
            const float a  = __ldg(&gamma[o]) * rsqrtf(__ldg(&var[o]) + EPSV);
            const float bb = __ldg(&b1[o]) * a + __ldg(&beta[o]) - __ldg(&mean[o]) * a;
            const float2 p0 = unpack2(qa[u]);
            const float2 p1 = unpack2(qb[u]);
            float4 r;
            r.x = fmaxf(p0.x * a + bb, 0.f);
            r.y = fmaxf(p0.y * a + bb, 0.f);
            r.z = fmaxf(p1.x * a + bb, 0.f);
            r.w = fmaxf(p1.y * a + bb, 0.f);
            *(float4*)&t_buf[((b * CR + o) * HW + h0 + py) * HW + w0 + pw] = r;
        }
    }
}

// ===========================================================================
// Kernel B: warp-specialized pipelined kernel-GEMM + involution
// ===========================================================================
__global__ void __launch_bounds__(256) involution_kernel(
    const float* __restrict__ x,
    const float* __restrict__ W2, const float* __restrict__ b2,
    float* __restrict__ out)
{
    extern __shared__ float smem[];
    float* ts = smem + B_OFF_TS;                    // [64cc][32px]
    ulonglong2* W2d = (ulonglong2*)(smem + B_OFF_W2D); // [cc][26] dup pairs
    float* wgbuf = smem + B_OFF_WG;                 // 2 x [49k][32px]
    float* xh = smem + B_OFF_XH;                    // [16c][10][16]

    const int tid = threadIdx.x;
    const int z   = blockIdx.z;
    const int b   = z >> 2;
    const int gbase = (z & 3) * GPB;
    const int h0  = blockIdx.y * TH;
    const int w0  = blockIdx.x * TW;

    const bool producer = (tid < 128);
    const int  ptid = tid;          // producer lane id (0..127)
    const int  ctid = tid - 128;    // consumer lane id (0..127)

    // ---------------- prologue ------------------------------------------
    if (producer) {
        // ts tile via cp.async16 (512 segments, 4 per thread)
        int idx = ptid;
        #pragma unroll
        for (int r = 0; r < 4; r++) {
            const int cc = idx >> 3, py = (idx >> 1) & 3, hf = idx & 1;
            cp_async16(&ts[cc * TP + py * TW + hf * 4],
                       &t_buf[((b * CR + cc) * HW + h0 + py) * HW + w0 + hf * 4]);
            idx += 128;
        }
        cp_commit();
        // stage W2d(group gbase): [cc][26] dup pairs, 1664 units, 13/thread
        {
            int u = ptid;
            #pragma unroll
            for (int r = 0; r < 13; r++) {
                const int cc = u & 63, p = u >> 6;
                const int k0 = 2 * p, k1 = 2 * p + 1;
                const float v0 = (k0 < 49) ? __ldg(&W2[(gbase * 49 + k0) * CR + cc]) : 0.f;
                const float v1 = (k1 < 49) ? __ldg(&W2[(gbase * 49 + k1) * CR + cc]) : 0.f;
                *(float4*)&W2d[cc * W2D_ROW + p] = make_float4(v0, v0, v1, v1);
                u += 128;
            }
        }
        cp_wait0();
        barx(1);            // producers: ts + W2d(g0) ready
    } else {
        // issue halo(group gbase): 640 segments, 5 per thread
        const float* xgb = &x[(size_t)(b * C + gbase * Cg) * HW * HW];
        int idx = ctid;
        #pragma unroll
        for (int r = 0; r < 5; r++) {
            const int c   = idx / 40;
            const int rem = idx - c * 40;
            const int rr  = rem >> 2;
            const int s   = rem & 3;
            const int gh  = h0 + rr - PAD;
            const int gw0 = w0 - 4 + 4 * s;
            int szb = 0;
            if ((unsigned)gh < (unsigned)HW && gw0 >= 0) {
                const int rem2 = HW - gw0;
                szb = (rem2 >= 4 ? 4 : (rem2 > 0 ? rem2 : 0)) * 4;
            }
            const int ghc = gh < 0 ? 0 : (gh > HW - 1 ? HW - 1 : gh);
            const int gwc = gw0 < 0 ? 0 : (gw0 > HW - 4 ? HW - 4 : gw0);
            cp_async16z(&xh[c * HALO_CH + rr * HALO_WP + 4 * s],
                        &xgb[(c * HW + ghc) * HW + gwc], szb);
            idx += 128;
        }
        cp_commit();
    }

    // producer phase-2 ids (identical active set to R7)
    const int kq   = ptid >> 3;       // active kq<13
    const int pxq2 = ptid & 7;
    // consumer phase-3 ids
    const int cs   = ctid >> 4;
    const int pxp  = ctid & 15;
    const int py3  = pxp >> 2;
    const int col3 = (pxp & 3) * 2;

    // ---------------- pipeline: i = 0..GPB ------------------------------
    for (int i = 0; i <= GPB; i++) {
        if (producer) {
            if (i < GPB) {
                const int g = gbase + i;
                float* wg = wgbuf + (i & 1) * WG_SZ;
                // phase 2 (R7 verbatim)
                if (kq < 13) {
                    const int kbase = 4 * kq;
                    float zb[4];
                    #pragma unroll
                    for (int kk = 0; kk < 4; kk++) {
                        const int k = kbase + kk;
                        zb[kk] = (k < 49) ? __ldg(&b2[g * 49 + k]) : 0.f;
                    }
                    U64 q0a = pack2(zb[0], zb[0]), q0b = q0a;
                    U64 q1a = pack2(zb[1], zb[1]), q1b = q1a;
                    U64 q2a = pack2(zb[2], zb[2]), q2b = q2a;
                    U64 q3a = pack2(zb[3], zb[3]), q3b = q3a;
                    #pragma unroll 8
                    for (int cc = 0; cc < 64; cc++) {
                        const ulonglong2 tv  = *(const ulonglong2*)&ts[cc * TP + pxq2 * 4];
                        const ulonglong2 wva = W2d[cc * W2D_ROW + 2 * kq];
                        const ulonglong2 wvb = W2d[cc * W2D_ROW + 2 * kq + 1];
                        q0a = ffma2(wva.x, tv.x, q0a); q0b = ffma2(wva.x, tv.y, q0b);
                        q1a = ffma2(wva.y, tv.x, q1a); q1b = ffma2(wva.y, tv.y, q1b);
                        q2a = ffma2(wvb.x, tv.x, q2a); q2b = ffma2(wvb.x, tv.y, q2b);
                        q3a = ffma2(wvb.y, tv.x, q3a); q3b = ffma2(wvb.y, tv.y, q3b);
                    }
                    U64 qa[4] = {q0a, q1a, q2a, q3a};
                    U64 qb[4] = {q0b, q1b, q2b, q3b};
                    #pragma unroll
                    for (int kk = 0; kk < 4; kk++) {
                        const int k = kbase + kk;
                        if (k < 49) {
                            *(U64*)&wg[k * TP + pxq2 * 4]     = qa[kk];
                            *(U64*)&wg[k * TP + pxq2 * 4 + 2] = qb[kk];
                        }
                    }
                }
                barx(1);        // all producers done reading W2d(g)
                if (i + 1 < GPB) {
                    // stage W2d(g+1)
                    const int gn = g + 1;
                    int u = ptid;
                    #pragma unroll
                    for (int r = 0; r < 13; r++) {
                        const int cc = u & 63, p = u >> 6;
                        const int k0 = 2 * p, k1 = 2 * p + 1;
                        const float v0 = (k0 < 49) ? __ldg(&W2[(gn * 49 + k0) * CR + cc]) : 0.f;
                        const float v1 = (k1 < 49) ? __ldg(&W2[(gn * 49 + k1) * CR + cc]) : 0.f;
                        *(float4*)&W2d[cc * W2D_ROW + p] = make_float4(v0, v0, v1, v1);
                        u += 128;
                    }
                }
            }
        } else {
            if (i >= 1) {
                const int g = gbase + i - 1;
                const float* wg = wgbuf + ((i - 1) & 1) * WG_SZ;
                cp_wait0();     // halo(g) landed (own FIFO)
                barx(2);        // all consumers' halo segments visible
                // phase 3 (R7 verbatim)
                {
                    const int c0 = 2 * cs;
                    const float* xa = &xh[c0 * HALO_CH + py3 * HALO_WP + col3];
                    const float* xb = xa + HALO_CH;
                    float o00 = 0.f, o01 = 0.f, o10 = 0.f, o11 = 0.f;
                    #pragma unroll
                    for (int ii = 0; ii < KS; ii++) {
                        const float* r0 = xa + ii * HALO_WP;
                        const float* r1 = xb + ii * HALO_WP;
                        float x0[10], x1[10];
                        #pragma unroll
                        for (int q = 0; q < 5; q++) {
                            const float2 v0 = *(const float2*)(r0 + 2 * q);
                            const float2 v1 = *(const float2*)(r1 + 2 * q);
                            x0[2 * q] = v0.x; x0[2 * q + 1] = v0.y;
                            x1[2 * q] = v1.x; x1[2 * q + 1] = v1.y;
                        }
                        #pragma unroll
                        for (int j = 0; j < KS; j++) {
                            const float2 wv = *(const float2*)&wg[(ii * KS + j) * TP + 2 * pxp];
                            o00 = fmaf(x0[j + 1], wv.x, o00);
                            o01 = fmaf(x0[j + 2], wv.y, o01);
                            o10 = fmaf(x1[j + 1], wv.x, o10);
                            o11 = fmaf(x1[j + 2], wv.y, o11);
                        }
                    }
                    const int base = ((b * C + g * Cg + c0) * HW + h0 + py3) * HW + w0 + col3;
                    *(float2*)&out[base]           = make_float2(o00, o01);
                    *(float2*)&out[base + HW * HW] = make_float2(o10, o11);
                }
                barx(2);        // all consumers done reading xh(g)
                if (i < GPB) {
                    // issue halo(gbase+i) into the single xh buffer
                    const int gn = gbase + i;
                    const float* xgb = &x[(size_t)(b * C + gn * Cg) * HW * HW];
                    int idx = ctid;
                    #pragma unroll
                    for (int r = 0; r < 5; r++) {
                        const int c   = idx / 40;
                        const int rem = idx - c * 40;
                        const int rr  = rem >> 2;
                        const int s   = rem & 3;
                        const int gh  = h0 + rr - PAD;
                        const int gw0 = w0 - 4 + 4 * s;
                        int szb = 0;
                        if ((unsigned)gh < (unsigned)HW && gw0 >= 0) {
                            const int rem2 = HW - gw0;
                            szb = (rem2 >= 4 ? 4 : (rem2 > 0 ? rem2 : 0)) * 4;
                        }
                        const int ghc = gh < 0 ? 0 : (gh > HW - 1 ? HW - 1 : gh);
                        const int gwc = gw0 < 0 ? 0 : (gw0 > HW - 4 ? HW - 4 : gw0);
                        cp_async16z(&xh[c * HALO_CH + rr * HALO_WP + 4 * s],
                                    &xgb[(c * HW + ghc) * HW + gwc], szb);
                        idx += 128;
                    }
                    cp_commit();
                }
            }
        }
        __syncthreads();   // publish wg(i) to consumers; step the pipeline
    }
}

extern "C" void kernel_launch(void* const* d_in, const int* in_sizes, int n_in,
                              void* d_out, int out_size) {
    const float* x     = (const float*)d_in[0];
    const float* W1    = (const float*)d_in[1];
    const float* b1    = (const float*)d_in[2];
    const float* gamma = (const float*)d_in[3];
    const float* beta  = (const float*)d_in[4];
    const float* mean  = (const float*)d_in[5];
    const float* var   = (const float*)d_in[6];
    const float* W2    = (const float*)d_in[7];
    const float* b2    = (const float*)d_in[8];
    float* out = (float*)d_out;

    const size_t smemA = (size_t)A_SMEM_FLOATS * sizeof(float);
    const size_t smemB = (size_t)B_SMEM_FLOATS * sizeof(float);
    cudaFuncSetAttribute(t_gemm_kernel,
                         cudaFuncAttributeMaxDynamicSharedMemorySize, (int)smemA);
    cudaFuncSetAttribute(involution_kernel,
                         cudaFuncAttributeMaxDynamicSharedMemorySize, (int)smemB);

    dim3 gridA(HW / TW, HW / TH, 4);            // 392 blocks
    t_gemm_kernel<<<gridA, 256, smemA>>>(x, W1, b1, gamma, beta, mean, var);

    dim3 gridB(HW / TW, HW / TH, 4 * SPLIT);    // 1568 blocks
    involution_kernel<<<gridB, 256, smemB>>>(x, W2, b2, out);
}